// round 6
// baseline (speedup 1.0000x reference)
#include <cuda_runtime.h>
#include <cstddef>
#include <cstdint>

// Problem constants:
//   C_IN=8, H=W=32, C_OUT=32, K=4, S=2, P=1, HO=WO=16
//   IN_FEAT = 8192, OUT_FEAT = 8192
// Output layout (flattened tuple):
//   [0, 16384)                    : out_bounds [2, 32, 16, 16]
//   [16384, 16384 + 8192*8192)    : W_mat [8192, 8192]
//   [16384 + 8192*8192, +8192)    : bias_backsub [8192]

#define C_IN     8
#define C_OUT    32
#define IN_FEAT  8192
#define OUT_FEAT 8192
#define WMAT_OFF 16384ULL
#define BB_OFF   (16384ULL + 8192ULL * 8192ULL)

#define FILL_BLOCKS   2368       // 148 SMs * 16
#define BOUNDS_BLOCKS 32
#define BLOCK_THREADS 256
#define WARPS_PER_BLOCK (BLOCK_THREADS / 32)

// W_mat in 4KB "chunks": one chunk = one (row o, input channel ci)
// = 32h x 32w floats. Total = 8192 rows * 8 ci = 65536 chunks.
#define TOTAL_CHUNKS 65536u

// 256-bit store (sm_100+): 8 x b32 per thread -> 1KB per warp instruction.
__device__ __forceinline__ void st256(float* p, const float v[8]) {
    asm volatile(
        "st.global.v8.b32 [%0], {%1,%2,%3,%4,%5,%6,%7,%8};"
        :: "l"(p),
           "r"(__float_as_uint(v[0])), "r"(__float_as_uint(v[1])),
           "r"(__float_as_uint(v[2])), "r"(__float_as_uint(v[3])),
           "r"(__float_as_uint(v[4])), "r"(__float_as_uint(v[5])),
           "r"(__float_as_uint(v[6])), "r"(__float_as_uint(v[7]))
        : "memory");
}

__global__ void __launch_bounds__(BLOCK_THREADS)
fused_deeppoly_kernel(const float* __restrict__ bounds,   // [2, 8192] (l, u)
                      const float* __restrict__ weight,   // [32, 8, 4, 4]
                      const float* __restrict__ bias,     // [32]
                      float* __restrict__ out) {
    unsigned bid = blockIdx.x;
    unsigned tid = threadIdx.x;

    if (bid >= FILL_BLOCKS) {
        // ------------------------------------------------------------------
        // Interval conv bounds (32 trailing blocks). Equals both the
        // forward-propagated and back-substituted bounds -> reference's
        // tighten is a no-op (verified R1-R5, rel_err 2e-7).
        // ------------------------------------------------------------------
        unsigned o = (bid - FILL_BLOCKS) * BLOCK_THREADS + tid;  // < 8192
        unsigned co = o >> 8;
        unsigned ho = (o >> 4) & 15u;
        unsigned wo = o & 15u;

        const float* __restrict__ l = bounds;
        const float* __restrict__ u = bounds + IN_FEAT;

        float b = __ldg(&bias[co]);
        float lo = b;
        float up = b;

        #pragma unroll
        for (int ci = 0; ci < C_IN; ci++) {
            #pragma unroll
            for (int kh = 0; kh < 4; kh++) {
                int h = 2 * (int)ho - 1 + kh;
                if ((unsigned)h >= 32u) continue;
                #pragma unroll
                for (int kw = 0; kw < 4; kw++) {
                    int w = 2 * (int)wo - 1 + kw;
                    if ((unsigned)w >= 32u) continue;
                    float wv = __ldg(&weight[co * 128u + (unsigned)ci * 16u +
                                             (unsigned)kh * 4u + (unsigned)kw]);
                    float wp = fmaxf(wv, 0.0f);
                    float wm = fminf(wv, 0.0f);
                    unsigned in = (unsigned)ci * 1024u +
                                  (unsigned)h * 32u + (unsigned)w;
                    float lv = __ldg(&l[in]);
                    float uv = __ldg(&u[in]);
                    lo = fmaf(wp, lv, fmaf(wm, uv, lo));
                    up = fmaf(wp, uv, fmaf(wm, lv, up));
                }
            }
        }

        out[o] = lo;                 // out_bounds[0]
        out[OUT_FEAT + o] = up;      // out_bounds[1]
        out[BB_OFF + o] = b;         // bias_backsub
        return;
    }

    // ----------------------------------------------------------------------
    // Fill+scatter: one warp per 4KB chunk (grid-stride). Chunk body = 4
    // warp-wide 256-bit stores (1KB/warp-instr). Each thread covers 8
    // consecutive floats = fixed h-row, w in [w0, w0+8):
    //   element e = it*32 + lane; h = e>>2 = it*8 + (lane>>2); w0 = (lane&3)*8
    // The "strip [8it, 8it+8) intersects window [hwin0, hwin0+4)" test is
    // warp-uniform; 2-3 of 4 iterations are pure zero stores.
    // ----------------------------------------------------------------------
    float* __restrict__ wmat = out + WMAT_OFF;

    unsigned lane = tid & 31u;
    unsigned warp = bid * WARPS_PER_BLOCK + (tid >> 5);
    const unsigned nwarps = FILL_BLOCKS * WARPS_PER_BLOCK;

    for (unsigned chunk = warp; chunk < TOTAL_CHUNKS; chunk += nwarps) {
        unsigned o  = chunk >> 3;
        unsigned ci = chunk & 7u;
        unsigned co = o >> 8;
        unsigned ho = (o >> 4) & 15u;
        unsigned wo = o & 15u;

        float* __restrict__ base = wmat + (size_t)chunk * 1024u;
        const float* __restrict__ wrow = weight + co * 128u + ci * 16u;

        int hwin0 = 2 * (int)ho - 1;                 // window h start
        int wwin0 = 2 * (int)wo - 1;                 // window w start
        int hl = (int)(lane >> 2);                   // 0..7 (h within strip)
        int kw0 = (int)((lane & 3u) << 3) - wwin0;   // kw of this thread's j=0

        #pragma unroll
        for (int it = 0; it < 4; it++) {
            float v[8] = {0.f, 0.f, 0.f, 0.f, 0.f, 0.f, 0.f, 0.f};
            // Warp-uniform: strip [8it, 8it+8) vs window [hwin0, hwin0+4)
            if (hwin0 + 3 >= 8 * it && hwin0 <= 8 * it + 7) {
                int kh = 8 * it + hl - hwin0;
                // thread's 8-float span [w0, w0+8) vs window [wwin0, wwin0+4)
                if ((unsigned)kh < 4u && kw0 > -8 && kw0 < 4) {
                    const float* __restrict__ wp = wrow + (unsigned)kh * 4u;
                    #pragma unroll
                    for (int j = 0; j < 8; j++) {
                        if ((unsigned)(kw0 + j) < 4u) v[j] = __ldg(&wp[kw0 + j]);
                    }
                }
            }
            st256(base + it * 256 + lane * 8, v);   // 1KB per warp-instr
        }
    }
}

extern "C" void kernel_launch(void* const* d_in, const int* in_sizes, int n_in,
                              void* d_out, int out_size) {
    const float* bounds = (const float*)d_in[0];  // [2, 8, 32, 32]
    const float* weight = (const float*)d_in[1];  // [32, 8, 4, 4]
    const float* bias   = (const float*)d_in[2];  // [32]
    // d_in[3] = assignment (unused by reference forward)

    float* out = (float*)d_out;

    fused_deeppoly_kernel<<<FILL_BLOCKS + BOUNDS_BLOCKS, BLOCK_THREADS>>>(
        bounds, weight, bias, out);
}

// round 7
// speedup vs baseline: 1.1944x; 1.1944x over previous
#include <cuda_runtime.h>
#include <cstddef>

// Problem constants:
//   C_IN=8, H=W=32, C_OUT=32, K=4, S=2, P=1, HO=WO=16
//   IN_FEAT = 8192, OUT_FEAT = 8192
// Output layout (flattened tuple):
//   [0, 16384)                    : out_bounds [2, 32, 16, 16]
//   [16384, 16384 + 8192*8192)    : W_mat [8192, 8192]
//   [16384 + 8192*8192, +8192)    : bias_backsub [8192]

#define C_IN     8
#define C_OUT    32
#define IN_FEAT  8192
#define OUT_FEAT 8192
#define WMAT_OFF 16384ULL
#define BB_OFF   (16384ULL + 8192ULL * 8192ULL)

#define BOUNDS_BLOCKS 32
#define FILL_BLOCKS   2048       // 16384 warps -> exactly 4 chunks per warp
#define BLOCK_THREADS 256
#define WARPS_PER_BLOCK (BLOCK_THREADS / 32)

// W_mat in 4KB "chunks": one chunk = one (row o, input channel ci)
// = 32h x 32w floats = 256 float4. Total = 8192 rows * 8 ci = 65536 chunks.
// Each warp owns 4 CONSECUTIVE chunks (16KB contiguous). A 4-aligned group
// of chunks never crosses a row boundary (8 chunks per row), so the row
// decomposition is done once per warp.

__global__ void __launch_bounds__(BLOCK_THREADS)
fused_deeppoly_kernel(const float* __restrict__ bounds,   // [2, 8192] (l, u)
                      const float* __restrict__ weight,   // [32, 8, 4, 4]
                      const float* __restrict__ bias,     // [32]
                      float* __restrict__ out) {
    unsigned bid = blockIdx.x;
    unsigned tid = threadIdx.x;

    if (bid < BOUNDS_BLOCKS) {
        // ------------------------------------------------------------------
        // Interval conv bounds. Equals both forward-propagated and
        // back-substituted bounds -> reference's tighten is a no-op
        // (verified R1-R6, rel_err 2e-7).
        // ------------------------------------------------------------------
        unsigned o = bid * BLOCK_THREADS + tid;      // < 8192
        unsigned co = o >> 8;
        unsigned ho = (o >> 4) & 15u;
        unsigned wo = o & 15u;

        const float* __restrict__ l = bounds;
        const float* __restrict__ u = bounds + IN_FEAT;

        float b = __ldg(&bias[co]);
        float lo = b;
        float up = b;

        #pragma unroll
        for (int ci = 0; ci < C_IN; ci++) {
            #pragma unroll
            for (int kh = 0; kh < 4; kh++) {
                int h = 2 * (int)ho - 1 + kh;
                if ((unsigned)h >= 32u) continue;
                #pragma unroll
                for (int kw = 0; kw < 4; kw++) {
                    int w = 2 * (int)wo - 1 + kw;
                    if ((unsigned)w >= 32u) continue;
                    float wv = __ldg(&weight[co * 128u + (unsigned)ci * 16u +
                                             (unsigned)kh * 4u + (unsigned)kw]);
                    float wp = fmaxf(wv, 0.0f);
                    float wm = fminf(wv, 0.0f);
                    unsigned in = (unsigned)ci * 1024u +
                                  (unsigned)h * 32u + (unsigned)w;
                    float lv = __ldg(&l[in]);
                    float uv = __ldg(&u[in]);
                    lo = fmaf(wp, lv, fmaf(wm, uv, lo));
                    up = fmaf(wp, uv, fmaf(wm, lv, up));
                }
            }
        }

        out[o] = lo;                 // out_bounds[0]
        out[OUT_FEAT + o] = up;      // out_bounds[1]
        out[BB_OFF + o] = b;         // bias_backsub
        return;
    }

    // ----------------------------------------------------------------------
    // Fill+scatter: each warp writes 4 consecutive 4KB chunks (one 16KB
    // contiguous region) as 4 x 8 warp-wide STG.128 (512B each, __stcs).
    // Row decomposition hoisted: group of 4 chunks shares (o, co, ho, wo);
    // only ci varies. The "strip intersects conv window" test is
    // warp-uniform; ~26 of 32 stores are pure zero stores.
    //
    // Within a chunk (fixed o, ci): float index = h*32 + w.
    // Iteration it covers h in [4*it, 4*it+4); lane covers
    // h = 4*it + (lane>>3), w in [4*(lane&7), 4*(lane&7)+4).
    // Nonzero iff kh = h-(2*ho-1) in [0,4) and kw = w-(2*wo-1) in [0,4).
    // ----------------------------------------------------------------------
    float4* __restrict__ wmat4 = (float4*)(out + WMAT_OFF);

    unsigned lane = tid & 31u;
    unsigned warp = (bid - BOUNDS_BLOCKS) * WARPS_PER_BLOCK + (tid >> 5);
    unsigned chunk0 = warp * 4u;                 // 4-aligned group

    unsigned o   = chunk0 >> 3;                  // same row for all 4 chunks
    unsigned ci0 = chunk0 & 7u;                  // 0 or 4
    unsigned co = o >> 8;
    unsigned ho = (o >> 4) & 15u;
    unsigned wo = o & 15u;

    const float* __restrict__ wbase = weight + co * 128u + ci0 * 16u;
    float4* __restrict__ gbase = wmat4 + (size_t)chunk0 * 256u;

    int hwin0 = 2 * (int)ho - 1;                     // window h start
    int kw0 = (int)((lane & 7u) << 2) - 2 * (int)wo + 1;
    int hl = (int)(lane >> 3);                       // 0..3
    bool wok = (kw0 > -4) && (kw0 < 4);              // thread's w-span hits window

    #pragma unroll
    for (int c = 0; c < 4; c++) {                    // ci = ci0 + c
        const float* __restrict__ wrow = wbase + c * 16;
        float4* __restrict__ base = gbase + c * 256;

        #pragma unroll
        for (int it = 0; it < 8; it++) {
            float4 v = make_float4(0.f, 0.f, 0.f, 0.f);
            // Warp-uniform: strip [4it, 4it+4) vs window [hwin0, hwin0+4)
            if (4 * it + 3 >= hwin0 && 4 * it <= hwin0 + 3) {
                int kh = 4 * it + hl - hwin0;
                if ((unsigned)kh < 4u && wok) {
                    const float* __restrict__ wp = wrow + (unsigned)kh * 4u;
                    if ((unsigned)(kw0 + 0) < 4u) v.x = __ldg(&wp[kw0 + 0]);
                    if ((unsigned)(kw0 + 1) < 4u) v.y = __ldg(&wp[kw0 + 1]);
                    if ((unsigned)(kw0 + 2) < 4u) v.z = __ldg(&wp[kw0 + 2]);
                    if ((unsigned)(kw0 + 3) < 4u) v.w = __ldg(&wp[kw0 + 3]);
                }
            }
            __stcs(&base[it * 32 + lane], v);        // streaming STG.128
        }
    }
}

extern "C" void kernel_launch(void* const* d_in, const int* in_sizes, int n_in,
                              void* d_out, int out_size) {
    const float* bounds = (const float*)d_in[0];  // [2, 8, 32, 32]
    const float* weight = (const float*)d_in[1];  // [32, 8, 4, 4]
    const float* bias   = (const float*)d_in[2];  // [32]
    // d_in[3] = assignment (unused by reference forward)

    float* out = (float*)d_out;

    fused_deeppoly_kernel<<<BOUNDS_BLOCKS + FILL_BLOCKS, BLOCK_THREADS>>>(
        bounds, weight, bias, out);
}